// round 3
// baseline (speedup 1.0000x reference)
#include <cuda_runtime.h>

#define N_TRAJ 512
#define P_DIM  256
#define CHUNKS 8
#define ROWS_PER_CTA (P_DIM / CHUNKS)   // 32
#define NW 8

// scratch: QNDG = M@(grad-gradm1), Mg = M@grad
__device__ float g_scrQ[N_TRAJ * P_DIM];
__device__ float g_scrM[N_TRAJ * P_DIM];
__device__ int   g_cnt[N_TRAJ];          // zero-init; reset by last finisher

__global__ __launch_bounds__(256, 3) void loa_fused_kernel(
    const float* __restrict__ grad,
    const float* __restrict__ gradm1,
    const float* __restrict__ dm1,
    const float* __restrict__ M,
    const float* __restrict__ Wfs,
    const float* __restrict__ Wo1,
    const float* __restrict__ Wo2,
    const float* __restrict__ Wo3,
    const float* __restrict__ Wl1,
    const float* __restrict__ Wl2,
    const float* __restrict__ Wl3,
    float* __restrict__ dout)
{
    const int b     = blockIdx.x;
    const int n     = b >> 3;
    const int chunk = b & 7;
    const int tid   = threadIdx.x;
    const int lane  = tid & 31;
    const int warp  = tid >> 5;

    __shared__ float s_w[516];
    __shared__ float s_red[NW][4];
    __shared__ float s_scal[8];
    __shared__ int   s_last;

    // ================= phase 1: mat-vec chunk (32 rows) =================
    {
        const float4* gg = reinterpret_cast<const float4*>(grad   + n * P_DIM);
        const float4* gm = reinterpret_cast<const float4*>(gradm1 + n * P_DIM);
        const float4 gv0 = gg[lane], gv1 = gg[32 + lane];
        const float4 m0  = gm[lane], m1  = gm[32 + lane];
        const float4 dv0 = make_float4(gv0.x - m0.x, gv0.y - m0.y, gv0.z - m0.z, gv0.w - m0.w);
        const float4 dv1 = make_float4(gv1.x - m1.x, gv1.y - m1.y, gv1.z - m1.z, gv1.w - m1.w);

        const int row0 = chunk * ROWS_PER_CTA + warp * 4;   // 4 rows per warp
        const float4* Mb = reinterpret_cast<const float4*>(M + (size_t)n * P_DIM * P_DIM)
                         + (size_t)row0 * (P_DIM / 4);

        // batch all 8 loads up front (MLP_p1 = 8)
        float4 a[4][2];
        #pragma unroll
        for (int r = 0; r < 4; ++r) {
            a[r][0] = Mb[(size_t)r * (P_DIM / 4) + lane];
            a[r][1] = Mb[(size_t)r * (P_DIM / 4) + 32 + lane];
        }

        #pragma unroll
        for (int r = 0; r < 4; ++r) {
            const float4 a0 = a[r][0], a1 = a[r][1];
            float s1 = a0.x * dv0.x + a0.y * dv0.y + a0.z * dv0.z + a0.w * dv0.w
                     + a1.x * dv1.x + a1.y * dv1.y + a1.z * dv1.z + a1.w * dv1.w;
            float s2 = a0.x * gv0.x + a0.y * gv0.y + a0.z * gv0.z + a0.w * gv0.w
                     + a1.x * gv1.x + a1.y * gv1.y + a1.z * gv1.z + a1.w * gv1.w;
            #pragma unroll
            for (int o = 16; o; o >>= 1) {
                s1 += __shfl_xor_sync(0xffffffffu, s1, o);
                s2 += __shfl_xor_sync(0xffffffffu, s2, o);
            }
            if (lane == 0) {
                g_scrQ[n * P_DIM + row0 + r] = s1;
                g_scrM[n * P_DIM + row0 + r] = s2;
            }
        }
    }

    // ================= completion protocol =================
    __threadfence();        // make scratch writes visible before the count
    __syncthreads();
    if (tid == 0) {
        int v = atomicAdd(&g_cnt[n], 1);
        s_last = (v == CHUNKS - 1);
        if (s_last) {
            g_cnt[n] = 0;   // reset for graph replay
            __threadfence();
        }
    }
    __syncthreads();
    if (!s_last) return;

    // ================= phase 2: epilogue (only last finisher per n) =====
    // stage weights
    for (int i = tid; i < 516; i += 256) {
        float w;
        if      (i < 6)   w = Wfs[i];
        else if (i < 24)  w = Wo1[i - 6];
        else if (i < 96)  w = Wo2[i - 24];
        else if (i < 132) w = Wo3[i - 96];
        else if (i < 204) w = Wl1[i - 132];
        else if (i < 492) w = Wl2[i - 204];
        else              w = Wl3[i - 492];
        s_w[i] = w;
    }

    const float gv  = grad[n * P_DIM + tid];
    const float dgk = gv - gradm1[n * P_DIM + tid];
    const float x0  = g_scrQ[n * P_DIM + tid];   // QNDG
    const float x1  = dm1[n * P_DIM + tid];
    const float Mg  = g_scrM[n * P_DIM + tid];
    const float x2  = -Mg;                       // Bg (GAMMA = 1)
    __syncthreads();

    // outer MLP
    const float* wo1 = s_w + 6;
    const float* wo2 = s_w + 24;
    const float* wo3 = s_w + 96;

    float h1[6];
    #pragma unroll
    for (int i = 0; i < 6; ++i) {
        float v = wo1[i*3+0]*x0 + wo1[i*3+1]*x1 + wo1[i*3+2]*x2;
        h1[i] = fmaxf(v, 0.0f);
    }
    float h2[12];
    #pragma unroll
    for (int i = 0; i < 12; ++i) {
        float v = 0.0f;
        #pragma unroll
        for (int j = 0; j < 6; ++j) v += wo2[i*6+j] * h1[j];
        h2[i] = fmaxf(v, 0.0f);
    }
    float of0 = 0.f, of1 = 0.f, of2 = 0.f;
    #pragma unroll
    for (int j = 0; j < 12; ++j) {
        of0 += wo3[0*12+j] * h2[j];
        of1 += wo3[1*12+j] * h2[j];
        of2 += wo3[2*12+j] * h2[j];
    }
    #pragma unroll
    for (int o = 16; o; o >>= 1) {
        of0 += __shfl_xor_sync(0xffffffffu, of0, o);
        of1 += __shfl_xor_sync(0xffffffffu, of1, o);
        of2 += __shfl_xor_sync(0xffffffffu, of2, o);
    }
    if (lane == 0) { s_red[warp][0] = of0; s_red[warp][1] = of1; s_red[warp][2] = of2; }
    __syncthreads();
    if (tid < 3) {
        float v = 0.0f;
        #pragma unroll
        for (int w = 0; w < NW; ++w) v += s_red[w][tid];
        s_scal[tid] = v * (1.0f / P_DIM);
    }
    __syncthreads();

    // full-skip + inner MLP
    const float f0 = s_scal[0], f1 = s_scal[1], f2 = s_scal[2];
    float x6[6] = {x0, x1, x2, f0, f1, f2};

    float fullskip = s_w[0]*x0 + s_w[1]*x1 + s_w[2]*x2
                   + s_w[3]*f0 + s_w[4]*f1 + s_w[5]*f2;

    const float* wl1 = s_w + 132;
    const float* wl2 = s_w + 204;
    const float* wl3 = s_w + 492;

    float l1[12];
    #pragma unroll
    for (int i = 0; i < 12; ++i) {
        float v = 0.0f;
        #pragma unroll
        for (int j = 0; j < 6; ++j) v += wl1[i*6+j] * x6[j];
        l1[i] = fmaxf(v, 0.0f);
    }
    float l2[24];
    #pragma unroll
    for (int i = 0; i < 24; ++i) {
        float v = 0.0f;
        #pragma unroll
        for (int j = 0; j < 12; ++j) v += wl2[i*12+j] * l1[j];
        l2[i] = fmaxf(v, 0.0f);
    }
    float out_p = fullskip;
    #pragma unroll
    for (int j = 0; j < 24; ++j) out_p += wl3[j] * l2[j];

    // BFGS scalars
    const float sec = x1 - x0;
    float r0 = out_p * dgk;
    float r1 = sec   * dgk;
    float r2 = out_p * gv;
    float r3 = sec   * gv;
    #pragma unroll
    for (int o = 16; o; o >>= 1) {
        r0 += __shfl_xor_sync(0xffffffffu, r0, o);
        r1 += __shfl_xor_sync(0xffffffffu, r1, o);
        r2 += __shfl_xor_sync(0xffffffffu, r2, o);
        r3 += __shfl_xor_sync(0xffffffffu, r3, o);
    }
    if (lane == 0) {
        s_red[warp][0] = r0; s_red[warp][1] = r1;
        s_red[warp][2] = r2; s_red[warp][3] = r3;
    }
    __syncthreads();
    if (tid < 4) {
        float v = 0.0f;
        #pragma unroll
        for (int w = 0; w < NW; ++w) v += s_red[w][tid];
        s_scal[4 + tid] = v;
    }
    __syncthreads();

    const float denom = s_scal[4];
    const float sdg   = s_scal[5];
    const float og    = s_scal[6];
    const float sg    = s_scal[7];
    const float norm  = 1.0f / denom;
    const float coef  = sdg * norm;

    float dval = -Mg - norm * (sec * og + out_p * sg - coef * out_p * og);
    dout[n * P_DIM + tid] = dval;
}

extern "C" void kernel_launch(void* const* d_in, const int* in_sizes, int n_in,
                              void* d_out, int out_size) {
    const float* grad   = (const float*)d_in[0];
    const float* gradm1 = (const float*)d_in[1];
    const float* dm1    = (const float*)d_in[2];
    const float* M      = (const float*)d_in[3];
    const float* Wfs    = (const float*)d_in[4];
    const float* Wo1    = (const float*)d_in[5];
    const float* Wo2    = (const float*)d_in[6];
    const float* Wo3    = (const float*)d_in[7];
    const float* Wl1    = (const float*)d_in[8];
    const float* Wl2    = (const float*)d_in[9];
    const float* Wl3    = (const float*)d_in[10];
    float* out = (float*)d_out;

    loa_fused_kernel<<<N_TRAJ * CHUNKS, 256>>>(grad, gradm1, dm1, M,
                                               Wfs, Wo1, Wo2, Wo3, Wl1, Wl2, Wl3, out);
}

// round 4
// speedup vs baseline: 1.0234x; 1.0234x over previous
#include <cuda_runtime.h>

#define N_TRAJ 512
#define P_DIM  256
#define CHUNKS 8
#define ROWS_PER_CTA (P_DIM / CHUNKS)       // 32
#define MV_BLOCKS (N_TRAJ * CHUNKS)         // 4096
#define NW 8

// scratch: QNDG = M@(grad-gradm1), Mg = M@grad
__device__ float g_scrQ[N_TRAJ * P_DIM];
__device__ float g_scrM[N_TRAJ * P_DIM];
__device__ int   g_cnt[N_TRAJ];             // zero-init; each consumer resets its own

__global__ __launch_bounds__(256, 3) void loa_overlap_kernel(
    const float* __restrict__ grad,
    const float* __restrict__ gradm1,
    const float* __restrict__ dm1,
    const float* __restrict__ M,
    const float* __restrict__ Wfs,
    const float* __restrict__ Wo1,
    const float* __restrict__ Wo2,
    const float* __restrict__ Wo3,
    const float* __restrict__ Wl1,
    const float* __restrict__ Wl2,
    const float* __restrict__ Wl3,
    float* __restrict__ dout)
{
    const int b    = blockIdx.x;
    const int tid  = threadIdx.x;
    const int lane = tid & 31;
    const int warp = tid >> 5;

    if (b < MV_BLOCKS) {
        // ================= producer: mat-vec chunk (32 rows) =================
        const int n     = b >> 3;
        const int chunk = b & 7;

        const float4* gg = reinterpret_cast<const float4*>(grad   + n * P_DIM);
        const float4* gm = reinterpret_cast<const float4*>(gradm1 + n * P_DIM);
        const float4 gv0 = gg[lane], gv1 = gg[32 + lane];
        const float4 m0  = gm[lane], m1  = gm[32 + lane];
        const float4 dv0 = make_float4(gv0.x - m0.x, gv0.y - m0.y, gv0.z - m0.z, gv0.w - m0.w);
        const float4 dv1 = make_float4(gv1.x - m1.x, gv1.y - m1.y, gv1.z - m1.z, gv1.w - m1.w);

        const int row0 = chunk * ROWS_PER_CTA + warp * 4;   // 4 rows per warp
        const float4* Mb = reinterpret_cast<const float4*>(M + (size_t)n * P_DIM * P_DIM)
                         + (size_t)row0 * (P_DIM / 4);

        // batch all 8 streaming loads up front (evict-first: M is read once)
        float4 a[4][2];
        #pragma unroll
        for (int r = 0; r < 4; ++r) {
            a[r][0] = __ldcs(&Mb[(size_t)r * (P_DIM / 4) + lane]);
            a[r][1] = __ldcs(&Mb[(size_t)r * (P_DIM / 4) + 32 + lane]);
        }

        #pragma unroll
        for (int r = 0; r < 4; ++r) {
            const float4 a0 = a[r][0], a1 = a[r][1];
            float s1 = a0.x * dv0.x + a0.y * dv0.y + a0.z * dv0.z + a0.w * dv0.w
                     + a1.x * dv1.x + a1.y * dv1.y + a1.z * dv1.z + a1.w * dv1.w;
            float s2 = a0.x * gv0.x + a0.y * gv0.y + a0.z * gv0.z + a0.w * gv0.w
                     + a1.x * gv1.x + a1.y * gv1.y + a1.z * gv1.z + a1.w * gv1.w;

            // dual reduction: lo half carries s1, hi half carries s2 (6 shfls)
            float send = (lane < 16) ? s2 : s1;
            float recv = __shfl_xor_sync(0xffffffffu, send, 16);
            float acc  = ((lane < 16) ? s1 : s2) + recv;
            #pragma unroll
            for (int o = 8; o; o >>= 1)
                acc += __shfl_xor_sync(0xffffffffu, acc, o);

            if (lane == 0)  g_scrQ[n * P_DIM + row0 + r] = acc;  // s1 sum
            if (lane == 16) g_scrM[n * P_DIM + row0 + r] = acc;  // s2 sum
        }

        // release: writer-side fence, then one flag bump per CTA
        if (lane == 0 || lane == 16) __threadfence();
        __syncthreads();
        if (tid == 0) atomicAdd(&g_cnt[n], 1);
        return;
    }

    // ================= consumer: epilogue for trajectory n =================
    const int n = b - MV_BLOCKS;

    __shared__ float s_w[516];
    __shared__ float s_red[NW][4];
    __shared__ float s_scal[8];

    // pre-stage everything that does not depend on the mat-vec
    for (int i = tid; i < 516; i += 256) {
        float w;
        if      (i < 6)   w = Wfs[i];
        else if (i < 24)  w = Wo1[i - 6];
        else if (i < 96)  w = Wo2[i - 24];
        else if (i < 132) w = Wo3[i - 96];
        else if (i < 204) w = Wl1[i - 132];
        else if (i < 492) w = Wl2[i - 204];
        else              w = Wl3[i - 492];
        s_w[i] = w;
    }
    const float gv  = grad[n * P_DIM + tid];
    const float dgk = gv - gradm1[n * P_DIM + tid];
    const float x1  = dm1[n * P_DIM + tid];

    // wait for all 8 producer chunks of this trajectory
    if (tid == 0) {
        volatile int* c = &g_cnt[n];
        while (*c != CHUNKS) __nanosleep(40);
        g_cnt[n] = 0;           // reset for next graph replay
        __threadfence();        // acquire side
    }
    __syncthreads();

    const float x0 = g_scrQ[n * P_DIM + tid];   // QNDG
    const float Mg = g_scrM[n * P_DIM + tid];
    const float x2 = -Mg;                       // Bg (GAMMA = 1)

    // ---- outer MLP + mean over P ----
    const float* wo1 = s_w + 6;
    const float* wo2 = s_w + 24;
    const float* wo3 = s_w + 96;

    float h1[6];
    #pragma unroll
    for (int i = 0; i < 6; ++i) {
        float v = wo1[i*3+0]*x0 + wo1[i*3+1]*x1 + wo1[i*3+2]*x2;
        h1[i] = fmaxf(v, 0.0f);
    }
    float h2[12];
    #pragma unroll
    for (int i = 0; i < 12; ++i) {
        float v = 0.0f;
        #pragma unroll
        for (int j = 0; j < 6; ++j) v += wo2[i*6+j] * h1[j];
        h2[i] = fmaxf(v, 0.0f);
    }
    float of0 = 0.f, of1 = 0.f, of2 = 0.f;
    #pragma unroll
    for (int j = 0; j < 12; ++j) {
        of0 += wo3[0*12+j] * h2[j];
        of1 += wo3[1*12+j] * h2[j];
        of2 += wo3[2*12+j] * h2[j];
    }
    #pragma unroll
    for (int o = 16; o; o >>= 1) {
        of0 += __shfl_xor_sync(0xffffffffu, of0, o);
        of1 += __shfl_xor_sync(0xffffffffu, of1, o);
        of2 += __shfl_xor_sync(0xffffffffu, of2, o);
    }
    if (lane == 0) { s_red[warp][0] = of0; s_red[warp][1] = of1; s_red[warp][2] = of2; }
    __syncthreads();
    if (tid < 3) {
        float v = 0.0f;
        #pragma unroll
        for (int w = 0; w < NW; ++w) v += s_red[w][tid];
        s_scal[tid] = v * (1.0f / P_DIM);
    }
    __syncthreads();

    // ---- full-skip + inner MLP ----
    const float f0 = s_scal[0], f1 = s_scal[1], f2 = s_scal[2];
    float x6[6] = {x0, x1, x2, f0, f1, f2};

    float fullskip = s_w[0]*x0 + s_w[1]*x1 + s_w[2]*x2
                   + s_w[3]*f0 + s_w[4]*f1 + s_w[5]*f2;

    const float* wl1 = s_w + 132;
    const float* wl2 = s_w + 204;
    const float* wl3 = s_w + 492;

    float l1[12];
    #pragma unroll
    for (int i = 0; i < 12; ++i) {
        float v = 0.0f;
        #pragma unroll
        for (int j = 0; j < 6; ++j) v += wl1[i*6+j] * x6[j];
        l1[i] = fmaxf(v, 0.0f);
    }
    float l2[24];
    #pragma unroll
    for (int i = 0; i < 24; ++i) {
        float v = 0.0f;
        #pragma unroll
        for (int j = 0; j < 12; ++j) v += wl2[i*12+j] * l1[j];
        l2[i] = fmaxf(v, 0.0f);
    }
    float out_p = fullskip;
    #pragma unroll
    for (int j = 0; j < 24; ++j) out_p += wl3[j] * l2[j];

    // ---- BFGS scalars ----
    const float sec = x1 - x0;
    float r0 = out_p * dgk;
    float r1 = sec   * dgk;
    float r2 = out_p * gv;
    float r3 = sec   * gv;
    #pragma unroll
    for (int o = 16; o; o >>= 1) {
        r0 += __shfl_xor_sync(0xffffffffu, r0, o);
        r1 += __shfl_xor_sync(0xffffffffu, r1, o);
        r2 += __shfl_xor_sync(0xffffffffu, r2, o);
        r3 += __shfl_xor_sync(0xffffffffu, r3, o);
    }
    if (lane == 0) {
        s_red[warp][0] = r0; s_red[warp][1] = r1;
        s_red[warp][2] = r2; s_red[warp][3] = r3;
    }
    __syncthreads();
    if (tid < 4) {
        float v = 0.0f;
        #pragma unroll
        for (int w = 0; w < NW; ++w) v += s_red[w][tid];
        s_scal[4 + tid] = v;
    }
    __syncthreads();

    const float denom = s_scal[4];
    const float sdg   = s_scal[5];
    const float og    = s_scal[6];
    const float sg    = s_scal[7];
    const float norm  = 1.0f / denom;
    const float coef  = sdg * norm;

    float dval = -Mg - norm * (sec * og + out_p * sg - coef * out_p * og);
    dout[n * P_DIM + tid] = dval;
}

extern "C" void kernel_launch(void* const* d_in, const int* in_sizes, int n_in,
                              void* d_out, int out_size) {
    const float* grad   = (const float*)d_in[0];
    const float* gradm1 = (const float*)d_in[1];
    const float* dm1    = (const float*)d_in[2];
    const float* M      = (const float*)d_in[3];
    const float* Wfs    = (const float*)d_in[4];
    const float* Wo1    = (const float*)d_in[5];
    const float* Wo2    = (const float*)d_in[6];
    const float* Wo3    = (const float*)d_in[7];
    const float* Wl1    = (const float*)d_in[8];
    const float* Wl2    = (const float*)d_in[9];
    const float* Wl3    = (const float*)d_in[10];
    float* out = (float*)d_out;

    loa_overlap_kernel<<<MV_BLOCKS + N_TRAJ, 256>>>(grad, gradm1, dm1, M,
                                                    Wfs, Wo1, Wo2, Wo3, Wl1, Wl2, Wl3, out);
}

// round 5
// speedup vs baseline: 1.1875x; 1.1603x over previous
#include <cuda_runtime.h>

#define N_TRAJ 512
#define P_DIM  256
#define CHUNKS 8
#define ROWS_PER_CTA (P_DIM / CHUNKS)   // 32
#define NW 8

typedef unsigned long long ull;

// scratch (L2-resident): QNDG = M@(grad-gradm1), Mg = M@grad, outer-MLP partials
__device__ float g_scrQ[N_TRAJ * P_DIM];
__device__ float g_scrM[N_TRAJ * P_DIM];
__device__ float g_ofp[N_TRAJ * CHUNKS * 4];   // per (n,chunk): partial of0..2

__device__ __forceinline__ ull pk(float lo, float hi) {
    ull r; asm("mov.b64 %0, {%1, %2};" : "=l"(r) : "f"(lo), "f"(hi)); return r;
}
__device__ __forceinline__ void upk(ull v, float& lo, float& hi) {
    asm("mov.b64 {%0, %1}, %2;" : "=f"(lo), "=f"(hi) : "l"(v));
}
__device__ __forceinline__ ull ffma2(ull a, ull b, ull c) {
    ull d; asm("fma.rn.f32x2 %0, %1, %2, %3;" : "=l"(d) : "l"(a), "l"(b), "l"(c)); return d;
}

// ---------------------------------------------------------------------------
// Kernel A: dual mat-vec (streams M once) + outer MLP in the memory shadow.
// 4096 CTAs x 256. Warp handles 4 rows, 8 LDG.128 batched up front.
// ---------------------------------------------------------------------------
__global__ __launch_bounds__(256, 3) void matvec_outer_kernel(
    const float* __restrict__ grad,
    const float* __restrict__ gradm1,
    const float* __restrict__ dm1,
    const float* __restrict__ M,
    const float* __restrict__ Wo1,     // (6,3)
    const float* __restrict__ Wo2,     // (12,6)
    const float* __restrict__ Wo3)     // (3,12)
{
    const int b     = blockIdx.x;
    const int n     = b >> 3;
    const int chunk = b & 7;
    const int tid   = threadIdx.x;
    const int lane  = tid & 31;
    const int warp  = tid >> 5;

    __shared__ float s_wo[126];        // [wo1 0:18 | wo2 18:90 | wo3 90:126]
    __shared__ float s_x0[ROWS_PER_CTA];
    __shared__ float s_mg[ROWS_PER_CTA];

    if (tid < 126) {
        float w;
        if      (tid < 18) w = Wo1[tid];
        else if (tid < 90) w = Wo2[tid - 18];
        else               w = Wo3[tid - 90];
        s_wo[tid] = w;
    }

    // ---- mat-vec chunk ----
    {
        const float4* gg = reinterpret_cast<const float4*>(grad   + n * P_DIM);
        const float4* gm = reinterpret_cast<const float4*>(gradm1 + n * P_DIM);
        const float4 gv0 = gg[lane], gv1 = gg[32 + lane];
        const float4 m0  = gm[lane], m1  = gm[32 + lane];
        const float4 dv0 = make_float4(gv0.x - m0.x, gv0.y - m0.y, gv0.z - m0.z, gv0.w - m0.w);
        const float4 dv1 = make_float4(gv1.x - m1.x, gv1.y - m1.y, gv1.z - m1.z, gv1.w - m1.w);

        const int row0 = chunk * ROWS_PER_CTA + warp * 4;
        const float4* Mb = reinterpret_cast<const float4*>(M + (size_t)n * P_DIM * P_DIM)
                         + (size_t)row0 * (P_DIM / 4);

        float4 a[4][2];
        #pragma unroll
        for (int r = 0; r < 4; ++r) {
            a[r][0] = __ldcs(&Mb[(size_t)r * (P_DIM / 4) + lane]);
            a[r][1] = __ldcs(&Mb[(size_t)r * (P_DIM / 4) + 32 + lane]);
        }

        #pragma unroll
        for (int r = 0; r < 4; ++r) {
            const float4 a0 = a[r][0], a1 = a[r][1];
            float s1 = a0.x * dv0.x + a0.y * dv0.y + a0.z * dv0.z + a0.w * dv0.w
                     + a1.x * dv1.x + a1.y * dv1.y + a1.z * dv1.z + a1.w * dv1.w;
            float s2 = a0.x * gv0.x + a0.y * gv0.y + a0.z * gv0.z + a0.w * gv0.w
                     + a1.x * gv1.x + a1.y * gv1.y + a1.z * gv1.z + a1.w * gv1.w;

            // dual reduction: lo half carries s1, hi half s2 (6 shfls)
            float send = (lane < 16) ? s2 : s1;
            float recv = __shfl_xor_sync(0xffffffffu, send, 16);
            float acc  = ((lane < 16) ? s1 : s2) + recv;
            #pragma unroll
            for (int o = 8; o; o >>= 1)
                acc += __shfl_xor_sync(0xffffffffu, acc, o);

            const int lrow = warp * 4 + r;
            if (lane == 0)  { g_scrQ[n * P_DIM + row0 + r] = acc; s_x0[lrow] = acc; }
            if (lane == 16) { g_scrM[n * P_DIM + row0 + r] = acc; s_mg[lrow] = acc; }
        }
    }
    __syncthreads();

    // ---- outer MLP for this chunk's 32 rows (warp 0 only; free under DRAM) ----
    if (tid < 32) {
        const float x0 = s_x0[tid];
        const float x1 = dm1[n * P_DIM + chunk * ROWS_PER_CTA + tid];
        const float x2 = -s_mg[tid];

        const float* wo1 = s_wo;
        const float* wo2 = s_wo + 18;
        const float* wo3 = s_wo + 90;

        float h1[6];
        #pragma unroll
        for (int i = 0; i < 6; ++i) {
            float v = wo1[i*3+0]*x0 + wo1[i*3+1]*x1 + wo1[i*3+2]*x2;
            h1[i] = fmaxf(v, 0.0f);
        }
        float h2[12];
        #pragma unroll
        for (int i = 0; i < 12; ++i) {
            float v = 0.0f;
            #pragma unroll
            for (int j = 0; j < 6; ++j) v += wo2[i*6+j] * h1[j];
            h2[i] = fmaxf(v, 0.0f);
        }
        float of0 = 0.f, of1 = 0.f, of2 = 0.f;
        #pragma unroll
        for (int j = 0; j < 12; ++j) {
            of0 += wo3[0*12+j] * h2[j];
            of1 += wo3[1*12+j] * h2[j];
            of2 += wo3[2*12+j] * h2[j];
        }
        #pragma unroll
        for (int o = 16; o; o >>= 1) {
            of0 += __shfl_xor_sync(0xffffffffu, of0, o);
            of1 += __shfl_xor_sync(0xffffffffu, of1, o);
            of2 += __shfl_xor_sync(0xffffffffu, of2, o);
        }
        if (tid == 0) {
            const int base = (n * CHUNKS + chunk) * 4;
            g_ofp[base + 0] = of0;
            g_ofp[base + 1] = of1;
            g_ofp[base + 2] = of2;
        }
    }
}

// ---------------------------------------------------------------------------
// Kernel B: inner MLP (f32x2-packed) + BFGS scalars + final d. 512 CTAs x 256.
// ---------------------------------------------------------------------------
__global__ __launch_bounds__(256, 4) void epilogue_kernel(
    const float* __restrict__ grad,
    const float* __restrict__ gradm1,
    const float* __restrict__ dm1,
    const float* __restrict__ Wfs,     // (1,6)
    const float* __restrict__ Wl1,     // (12,6)
    const float* __restrict__ Wl2,     // (24,12)
    const float* __restrict__ Wl3,     // (1,24)
    float* __restrict__ dout)
{
    const int n    = blockIdx.x;
    const int tid  = threadIdx.x;
    const int lane = tid & 31;
    const int warp = tid >> 5;
    const int idx  = n * P_DIM + tid;

    __shared__ float s_wfs[6];
    __shared__ ull   s_w1[36];    // pair k(0..5),  j(0..5):  (Wl1[2k][j],  Wl1[2k+1][j])
    __shared__ ull   s_w2[144];   // pair k(0..11), j(0..11): (Wl2[2k][j],  Wl2[2k+1][j])
    __shared__ ull   s_w3[12];    // j: (Wl3[2j], Wl3[2j+1])
    __shared__ float s_red[NW][4];
    __shared__ float s_scal[8];

    // early loads (L2-resident scratch + input vectors)
    const float x0  = g_scrQ[idx];
    const float Mg  = g_scrM[idx];
    const float gv  = grad[idx];
    const float dgk = gv - gradm1[idx];
    const float x1  = dm1[idx];

    // stage packed weights
    if (tid < 6) s_wfs[tid] = Wfs[tid];
    if (tid < 36) {
        int k = tid / 6, j = tid % 6;
        s_w1[tid] = pk(Wl1[(2*k)*6 + j], Wl1[(2*k+1)*6 + j]);
    } else if (tid < 180) {
        int t = tid - 36; int k = t / 12, j = t % 12;
        s_w2[t] = pk(Wl2[(2*k)*12 + j], Wl2[(2*k+1)*12 + j]);
    } else if (tid < 192) {
        int j = tid - 180;
        s_w3[j] = pk(Wl3[2*j], Wl3[2*j+1]);
    }
    // outer-MLP mean from per-chunk partials (fixed order -> deterministic)
    if (tid >= 252 && tid < 255) {
        const int c3 = tid - 252;
        float s = 0.0f;
        #pragma unroll
        for (int c = 0; c < CHUNKS; ++c) s += g_ofp[(n * CHUNKS + c) * 4 + c3];
        s_scal[c3] = s * (1.0f / P_DIM);
    }
    __syncthreads();

    const float f0 = s_scal[0], f1 = s_scal[1], f2 = s_scal[2];
    const float x2 = -Mg;

    float fullskip = s_wfs[0]*x0 + s_wfs[1]*x1 + s_wfs[2]*x2
                   + s_wfs[3]*f0 + s_wfs[4]*f1 + s_wfs[5]*f2;

    // duplicated inputs for pair-FMA
    ull xd[6];
    xd[0] = pk(x0, x0); xd[1] = pk(x1, x1); xd[2] = pk(x2, x2);
    xd[3] = pk(f0, f0); xd[4] = pk(f1, f1); xd[5] = pk(f2, f2);

    // layer 1: 12 neurons as 6 pairs
    ull l1d[12];
    #pragma unroll
    for (int k = 0; k < 6; ++k) {
        ull acc = 0ULL;
        #pragma unroll
        for (int j = 0; j < 6; ++j) acc = ffma2(s_w1[k*6 + j], xd[j], acc);
        float a, c; upk(acc, a, c);
        a = fmaxf(a, 0.0f); c = fmaxf(c, 0.0f);
        l1d[2*k]   = pk(a, a);
        l1d[2*k+1] = pk(c, c);
    }

    // layer 2 fused with layer 3: 24 neurons as 12 pairs, consumed immediately
    ull acc3 = 0ULL;
    #pragma unroll
    for (int k = 0; k < 12; ++k) {
        ull acc = 0ULL;
        #pragma unroll
        for (int j = 0; j < 12; ++j) acc = ffma2(s_w2[k*12 + j], l1d[j], acc);
        float a, c; upk(acc, a, c);
        a = fmaxf(a, 0.0f); c = fmaxf(c, 0.0f);
        acc3 = ffma2(s_w3[k], pk(a, c), acc3);
    }
    float ta, tb; upk(acc3, ta, tb);
    float out_p = fullskip + ta + tb;

    // ---- BFGS scalars ----
    const float sec = x1 - x0;
    float r0 = out_p * dgk;
    float r1 = sec   * dgk;
    float r2 = out_p * gv;
    float r3 = sec   * gv;
    #pragma unroll
    for (int o = 16; o; o >>= 1) {
        r0 += __shfl_xor_sync(0xffffffffu, r0, o);
        r1 += __shfl_xor_sync(0xffffffffu, r1, o);
        r2 += __shfl_xor_sync(0xffffffffu, r2, o);
        r3 += __shfl_xor_sync(0xffffffffu, r3, o);
    }
    if (lane == 0) {
        s_red[warp][0] = r0; s_red[warp][1] = r1;
        s_red[warp][2] = r2; s_red[warp][3] = r3;
    }
    __syncthreads();
    if (tid < 4) {
        float v = 0.0f;
        #pragma unroll
        for (int w = 0; w < NW; ++w) v += s_red[w][tid];
        s_scal[4 + tid] = v;
    }
    __syncthreads();

    const float denom = s_scal[4];
    const float sdg   = s_scal[5];
    const float og    = s_scal[6];
    const float sg    = s_scal[7];
    const float norm  = 1.0f / denom;
    const float coef  = sdg * norm;

    float dval = -Mg - norm * (sec * og + out_p * sg - coef * out_p * og);
    dout[idx] = dval;
}

extern "C" void kernel_launch(void* const* d_in, const int* in_sizes, int n_in,
                              void* d_out, int out_size) {
    const float* grad   = (const float*)d_in[0];
    const float* gradm1 = (const float*)d_in[1];
    const float* dm1    = (const float*)d_in[2];
    const float* M      = (const float*)d_in[3];
    const float* Wfs    = (const float*)d_in[4];
    const float* Wo1    = (const float*)d_in[5];
    const float* Wo2    = (const float*)d_in[6];
    const float* Wo3    = (const float*)d_in[7];
    const float* Wl1    = (const float*)d_in[8];
    const float* Wl2    = (const float*)d_in[9];
    const float* Wl3    = (const float*)d_in[10];
    float* out = (float*)d_out;

    matvec_outer_kernel<<<N_TRAJ * CHUNKS, 256>>>(grad, gradm1, dm1, M, Wo1, Wo2, Wo3);
    epilogue_kernel<<<N_TRAJ, 256>>>(grad, gradm1, dm1, Wfs, Wl1, Wl2, Wl3, out);
}

// round 6
// speedup vs baseline: 1.2618x; 1.0626x over previous
#include <cuda_runtime.h>

#define N_TRAJ 512
#define P_DIM  256
#define CHUNKS 8
#define ROWS_PER_CTA (P_DIM / CHUNKS)   // 32
#define NW 8

typedef unsigned long long ull;

// scratch (L2-resident): QNDG = M@(grad-gradm1), Mg = M@grad, outer-MLP partials
__device__ float g_scrQ[N_TRAJ * P_DIM];
__device__ float g_scrM[N_TRAJ * P_DIM];
__device__ float g_ofp[N_TRAJ * CHUNKS * 4];   // per (n,chunk): partial of0..2

__device__ __forceinline__ ull pk(float lo, float hi) {
    ull r; asm("mov.b64 %0, {%1, %2};" : "=l"(r) : "f"(lo), "f"(hi)); return r;
}
__device__ __forceinline__ void upk(ull v, float& lo, float& hi) {
    asm("mov.b64 {%0, %1}, %2;" : "=f"(lo), "=f"(hi) : "l"(v));
}
__device__ __forceinline__ ull ffma2(ull a, ull b, ull c) {
    ull d; asm("fma.rn.f32x2 %0, %1, %2, %3;" : "=l"(d) : "l"(a), "l"(b), "l"(c)); return d;
}

// ---------------------------------------------------------------------------
// Kernel A: dual mat-vec (streams M once) + outer MLP in the memory shadow.
// 4096 CTAs x 256. Octet-per-row layout: 3 shfls/warp instead of 24.
// ---------------------------------------------------------------------------
__global__ __launch_bounds__(256, 4) void matvec_outer_kernel(
    const float* __restrict__ grad,
    const float* __restrict__ gradm1,
    const float* __restrict__ dm1,
    const float* __restrict__ M,
    const float* __restrict__ Wo1,     // (6,3)
    const float* __restrict__ Wo2,     // (12,6)
    const float* __restrict__ Wo3)     // (3,12)
{
    const int b     = blockIdx.x;
    const int n     = b >> 3;
    const int chunk = b & 7;
    const int tid   = threadIdx.x;
    const int lane  = tid & 31;
    const int warp  = tid >> 5;

    __shared__ float s_g[P_DIM];
    __shared__ float s_dg[P_DIM];
    __shared__ float s_wo[126];        // [wo1 0:18 | wo2 18:90 | wo3 90:126]
    __shared__ float s_x0[ROWS_PER_CTA];
    __shared__ float s_mg[ROWS_PER_CTA];

    // stage vectors + weights
    {
        float gv = grad[n * P_DIM + tid];
        float gm = gradm1[n * P_DIM + tid];
        s_g[tid]  = gv;
        s_dg[tid] = gv - gm;
    }
    if (tid < 126) {
        float w;
        if      (tid < 18) w = Wo1[tid];
        else if (tid < 90) w = Wo2[tid - 18];
        else               w = Wo3[tid - 90];
        s_wo[tid] = w;
    }
    __syncthreads();

    // ---- mat-vec: octet (8 lanes) owns one row; 8 iterations cover 256 cols ----
    const int oc   = lane & 7;              // col-group within octet
    const int lrow = warp * 4 + (lane >> 3);
    const int row  = chunk * ROWS_PER_CTA + lrow;

    const float4* Mrow = reinterpret_cast<const float4*>(
        M + (size_t)n * P_DIM * P_DIM + (size_t)row * P_DIM);

    float4 a[8];
    #pragma unroll
    for (int it = 0; it < 8; ++it)
        a[it] = __ldcs(&Mrow[oc + it * 8]);

    const float4* g4  = reinterpret_cast<const float4*>(s_g);
    const float4* dg4 = reinterpret_cast<const float4*>(s_dg);

    float s1 = 0.0f, s2 = 0.0f;
    #pragma unroll
    for (int it = 0; it < 8; ++it) {
        const float4 aq = a[it];
        const float4 dq = dg4[oc + it * 8];
        const float4 gq = g4 [oc + it * 8];
        s1 += aq.x * dq.x + aq.y * dq.y + aq.z * dq.z + aq.w * dq.w;
        s2 += aq.x * gq.x + aq.y * gq.y + aq.z * gq.z + aq.w * gq.w;
    }

    // dual reduce within octet: 3 shfls for both sums, all rows at once
    float send = (lane & 4) ? s1 : s2;
    float recv = __shfl_xor_sync(0xffffffffu, send, 4);
    float acc  = ((lane & 4) ? s2 : s1) + recv;
    acc += __shfl_xor_sync(0xffffffffu, acc, 2);
    acc += __shfl_xor_sync(0xffffffffu, acc, 1);
    // lanes with (lane&7)==0 hold s1 (QNDG row sum); (lane&7)==4 hold s2 (Mg)
    if ((lane & 7) == 0) { g_scrQ[n * P_DIM + row] = acc; s_x0[lrow] = acc; }
    if ((lane & 7) == 4) { g_scrM[n * P_DIM + row] = acc; s_mg[lrow] = acc; }
    __syncthreads();

    // ---- outer MLP for this chunk's 32 rows (warp 0; free under DRAM) ----
    if (tid < 32) {
        const float x0 = s_x0[tid];
        const float x1 = dm1[n * P_DIM + chunk * ROWS_PER_CTA + tid];
        const float x2 = -s_mg[tid];

        const float* wo1 = s_wo;
        const float* wo2 = s_wo + 18;
        const float* wo3 = s_wo + 90;

        float h1[6];
        #pragma unroll
        for (int i = 0; i < 6; ++i) {
            float v = wo1[i*3+0]*x0 + wo1[i*3+1]*x1 + wo1[i*3+2]*x2;
            h1[i] = fmaxf(v, 0.0f);
        }
        float h2[12];
        #pragma unroll
        for (int i = 0; i < 12; ++i) {
            float v = 0.0f;
            #pragma unroll
            for (int j = 0; j < 6; ++j) v += wo2[i*6+j] * h1[j];
            h2[i] = fmaxf(v, 0.0f);
        }
        float of0 = 0.f, of1 = 0.f, of2 = 0.f;
        #pragma unroll
        for (int j = 0; j < 12; ++j) {
            of0 += wo3[0*12+j] * h2[j];
            of1 += wo3[1*12+j] * h2[j];
            of2 += wo3[2*12+j] * h2[j];
        }
        #pragma unroll
        for (int o = 16; o; o >>= 1) {
            of0 += __shfl_xor_sync(0xffffffffu, of0, o);
            of1 += __shfl_xor_sync(0xffffffffu, of1, o);
            of2 += __shfl_xor_sync(0xffffffffu, of2, o);
        }
        if (tid == 0) {
            const int base = (n * CHUNKS + chunk) * 4;
            g_ofp[base + 0] = of0;
            g_ofp[base + 1] = of1;
            g_ofp[base + 2] = of2;
        }
    }
}

// ---------------------------------------------------------------------------
// Kernel B: inner MLP (f32x2-packed) + BFGS scalars + final d. 512 CTAs x 256.
// ---------------------------------------------------------------------------
__global__ __launch_bounds__(256, 4) void epilogue_kernel(
    const float* __restrict__ grad,
    const float* __restrict__ gradm1,
    const float* __restrict__ dm1,
    const float* __restrict__ Wfs,     // (1,6)
    const float* __restrict__ Wl1,     // (12,6)
    const float* __restrict__ Wl2,     // (24,12)
    const float* __restrict__ Wl3,     // (1,24)
    float* __restrict__ dout)
{
    const int n    = blockIdx.x;
    const int tid  = threadIdx.x;
    const int lane = tid & 31;
    const int warp = tid >> 5;
    const int idx  = n * P_DIM + tid;

    __shared__ float s_wfs[6];
    __shared__ ull   s_w1[36];    // pair k(0..5),  j(0..5):  (Wl1[2k][j],  Wl1[2k+1][j])
    __shared__ ull   s_w2[144];   // pair k(0..11), j(0..11): (Wl2[2k][j],  Wl2[2k+1][j])
    __shared__ ull   s_w3[12];    // j: (Wl3[2j], Wl3[2j+1])
    __shared__ float s_red[NW][4];
    __shared__ float s_scal[8];

    // early loads (L2-resident scratch + input vectors)
    const float x0  = g_scrQ[idx];
    const float Mg  = g_scrM[idx];
    const float gv  = grad[idx];
    const float dgk = gv - gradm1[idx];
    const float x1  = dm1[idx];

    // stage packed weights
    if (tid < 6) s_wfs[tid] = Wfs[tid];
    if (tid < 36) {
        int k = tid / 6, j = tid % 6;
        s_w1[tid] = pk(Wl1[(2*k)*6 + j], Wl1[(2*k+1)*6 + j]);
    } else if (tid < 180) {
        int t = tid - 36; int k = t / 12, j = t % 12;
        s_w2[t] = pk(Wl2[(2*k)*12 + j], Wl2[(2*k+1)*12 + j]);
    } else if (tid < 192) {
        int j = tid - 180;
        s_w3[j] = pk(Wl3[2*j], Wl3[2*j+1]);
    }
    // outer-MLP mean from per-chunk partials (fixed order -> deterministic)
    if (tid >= 252 && tid < 255) {
        const int c3 = tid - 252;
        float s = 0.0f;
        #pragma unroll
        for (int c = 0; c < CHUNKS; ++c) s += g_ofp[(n * CHUNKS + c) * 4 + c3];
        s_scal[c3] = s * (1.0f / P_DIM);
    }
    __syncthreads();

    const float f0 = s_scal[0], f1 = s_scal[1], f2 = s_scal[2];
    const float x2 = -Mg;

    float fullskip = s_wfs[0]*x0 + s_wfs[1]*x1 + s_wfs[2]*x2
                   + s_wfs[3]*f0 + s_wfs[4]*f1 + s_wfs[5]*f2;

    // duplicated inputs for pair-FMA
    ull xd[6];
    xd[0] = pk(x0, x0); xd[1] = pk(x1, x1); xd[2] = pk(x2, x2);
    xd[3] = pk(f0, f0); xd[4] = pk(f1, f1); xd[5] = pk(f2, f2);

    // layer 1: 12 neurons as 6 pairs
    ull l1d[12];
    #pragma unroll
    for (int k = 0; k < 6; ++k) {
        ull acc = 0ULL;
        #pragma unroll
        for (int j = 0; j < 6; ++j) acc = ffma2(s_w1[k*6 + j], xd[j], acc);
        float a, c; upk(acc, a, c);
        a = fmaxf(a, 0.0f); c = fmaxf(c, 0.0f);
        l1d[2*k]   = pk(a, a);
        l1d[2*k+1] = pk(c, c);
    }

    // layer 2 fused with layer 3: 24 neurons as 12 pairs, consumed immediately
    ull acc3 = 0ULL;
    #pragma unroll
    for (int k = 0; k < 12; ++k) {
        ull acc = 0ULL;
        #pragma unroll
        for (int j = 0; j < 12; ++j) acc = ffma2(s_w2[k*12 + j], l1d[j], acc);
        float a, c; upk(acc, a, c);
        a = fmaxf(a, 0.0f); c = fmaxf(c, 0.0f);
        acc3 = ffma2(s_w3[k], pk(a, c), acc3);
    }
    float ta, tb; upk(acc3, ta, tb);
    float out_p = fullskip + ta + tb;

    // ---- BFGS scalars ----
    const float sec = x1 - x0;
    float r0 = out_p * dgk;
    float r1 = sec   * dgk;
    float r2 = out_p * gv;
    float r3 = sec   * gv;
    #pragma unroll
    for (int o = 16; o; o >>= 1) {
        r0 += __shfl_xor_sync(0xffffffffu, r0, o);
        r1 += __shfl_xor_sync(0xffffffffu, r1, o);
        r2 += __shfl_xor_sync(0xffffffffu, r2, o);
        r3 += __shfl_xor_sync(0xffffffffu, r3, o);
    }
    if (lane == 0) {
        s_red[warp][0] = r0; s_red[warp][1] = r1;
        s_red[warp][2] = r2; s_red[warp][3] = r3;
    }
    __syncthreads();
    if (tid < 4) {
        float v = 0.0f;
        #pragma unroll
        for (int w = 0; w < NW; ++w) v += s_red[w][tid];
        s_scal[4 + tid] = v;
    }
    __syncthreads();

    const float denom = s_scal[4];
    const float sdg   = s_scal[5];
    const float og    = s_scal[6];
    const float sg    = s_scal[7];
    const float norm  = 1.0f / denom;
    const float coef  = sdg * norm;

    float dval = -Mg - norm * (sec * og + out_p * sg - coef * out_p * og);
    dout[idx] = dval;
}

extern "C" void kernel_launch(void* const* d_in, const int* in_sizes, int n_in,
                              void* d_out, int out_size) {
    const float* grad   = (const float*)d_in[0];
    const float* gradm1 = (const float*)d_in[1];
    const float* dm1    = (const float*)d_in[2];
    const float* M      = (const float*)d_in[3];
    const float* Wfs    = (const float*)d_in[4];
    const float* Wo1    = (const float*)d_in[5];
    const float* Wo2    = (const float*)d_in[6];
    const float* Wo3    = (const float*)d_in[7];
    const float* Wl1    = (const float*)d_in[8];
    const float* Wl2    = (const float*)d_in[9];
    const float* Wl3    = (const float*)d_in[10];
    float* out = (float*)d_out;

    matvec_outer_kernel<<<N_TRAJ * CHUNKS, 256>>>(grad, gradm1, dm1, M, Wo1, Wo2, Wo3);
    epilogue_kernel<<<N_TRAJ, 256>>>(grad, gradm1, dm1, Wfs, Wl1, Wl2, Wl3, out);
}